// round 12
// baseline (speedup 1.0000x reference)
#include <cuda_runtime.h>
#include <cuda_fp16.h>
#include <cstdint>
#include <cstddef>

// ---------------------------------------------------------------------------
// SelfAttention on sm_103, mma.sync fp16, fp32 accumulate everywhere.
// R12: GEMMs back to 128x128 CTA tiles (1-term fits regs now): ldsm/MMA
// ratio 0.5 -> 0.375 and 2x operand reuse; R11's 64x128 tile left gemm1 at
// 80% of the HMMA ceiling (211.5 vs ~170 us). Attention/prep unchanged.
// Error scheme unchanged: rel_err 7.07e-4 (calibrated ledger, R8-R11).
// ---------------------------------------------------------------------------

#define Tn     2048
#define Cn     2048
#define QKVW   3072          // (16 + 2*4) * 128
#define ROWS   4096          // B*T
#define GK     2048          // K dim of both big GEMMs

typedef __half f16;

__device__ __align__(16) float g_qkv[(size_t)ROWS * QKVW];
__device__ __align__(16) f16  g_xh[(size_t)ROWS * GK];
__device__ __align__(16) f16  g_wah[(size_t)QKVW * GK];
__device__ __align__(16) f16  g_wph[(size_t)Cn * GK];
__device__ __align__(16) f16  g_qh[(size_t)2 * 16 * Tn * 128];
__device__ __align__(16) f16  g_kh[(size_t)2 * 4 * Tn * 128];
__device__ __align__(16) f16  g_vth[(size_t)2 * 4 * 128 * Tn];
__device__ __align__(16) f16  g_yh[(size_t)ROWS * Cn];

// 1/sqrt(128) * log2(e): softmax scale + exp->exp2, folded into q
#define QK_SCALE (0.08838834764831845f * 1.4426950408889634f)

// ============================ helpers =======================================
__device__ __forceinline__ float ex2f(float x) {
    float r;
    asm("ex2.approx.ftz.f32 %0, %1;" : "=f"(r) : "f"(x));
    return r;
}
__device__ __forceinline__ uint32_t pkh2(float lo, float hi) {
    __half2 h = __floats2half2_rn(lo, hi);
    return *reinterpret_cast<uint32_t*>(&h);
}
__device__ __forceinline__ void mma_f32a(float (&d)[4], const uint32_t (&a)[4],
                                         const uint32_t* b) {
    asm volatile(
        "mma.sync.aligned.m16n8k16.row.col.f32.f16.f16.f32 "
        "{%0,%1,%2,%3}, {%4,%5,%6,%7}, {%8,%9}, {%0,%1,%2,%3};"
        : "+f"(d[0]), "+f"(d[1]), "+f"(d[2]), "+f"(d[3])
        : "r"(a[0]), "r"(a[1]), "r"(a[2]), "r"(a[3]), "r"(b[0]), "r"(b[1]));
}
__device__ __forceinline__ void ldsm4(uint32_t* r, uint32_t a) {
    asm volatile("ldmatrix.sync.aligned.m8n8.x4.shared.b16 {%0,%1,%2,%3}, [%4];"
                 : "=r"(r[0]), "=r"(r[1]), "=r"(r[2]), "=r"(r[3]) : "r"(a));
}
__device__ __forceinline__ uint32_t smem_u32(const void* p) {
    uint32_t a;
    asm("{ .reg .u64 t; cvta.to.shared.u64 t, %1; cvt.u32.u64 %0, t; }"
        : "=r"(a) : "l"(p));
    return a;
}
#define CP16(dst, src) \
    asm volatile("cp.async.cg.shared.global [%0], [%1], 16;" \
                 :: "r"(dst), "l"(src) : "memory")
#define CPCOMMIT() asm volatile("cp.async.commit_group;" ::: "memory")
#define CPWAIT1()  asm volatile("cp.async.wait_group 1;" ::: "memory")
#define CPWAIT0()  asm volatile("cp.async.wait_group 0;" ::: "memory")

// ---------------------------------------------------------------------------
// convert x -> fp16
// ---------------------------------------------------------------------------
__global__ __launch_bounds__(256) void splitx_kernel(const float* __restrict__ x) {
    size_t i = ((size_t)blockIdx.x * 256 + threadIdx.x) * 4;
    float4 v = *(const float4*)(x + i);
    uint32_t p0 = pkh2(v.x, v.y), p1 = pkh2(v.z, v.w);
    *(uint2*)(g_xh + i) = make_uint2(p0, p1);
}

// ---------------------------------------------------------------------------
// transpose weights to fp16: in [2048][Ccols] fp32 -> [Ccols][2048]
// ---------------------------------------------------------------------------
__global__ __launch_bounds__(256) void wsplit_kernel(
    const float* __restrict__ in, f16* __restrict__ hi, int Ccols)
{
    __shared__ float tb[32][33];
    const int bx = blockIdx.x * 32, by = blockIdx.y * 32;
    const int tx = threadIdx.x, ty = threadIdx.y;
#pragma unroll
    for (int j = 0; j < 32; j += 8)
        tb[ty + j][tx] = in[(size_t)(by + ty + j) * Ccols + bx + tx];
    __syncthreads();
#pragma unroll
    for (int j = 0; j < 32; j += 8) {
        float v = tb[tx][ty + j];
        hi[(size_t)(bx + ty + j) * GK + by + tx] = __float2half_rn(v);
    }
}

// ---------------------------------------------------------------------------
// fp16 1-term GEMM: C[M,N] = A @ B^T, f32 accumulate.
// CTA tile 128x128, kchunk 32, cp.async double buffer, 8 warps (4m x 2n),
// warp tile 32x64. smem stage: A@0 (128 x 80B), B@10240 (128 x 80B).
// ---------------------------------------------------------------------------
#define GS_STAGE 20480
#define GSM (2 * GS_STAGE)

__global__ __launch_bounds__(256, 2) void hgemm1_kernel(
    const f16* __restrict__ A, const f16* __restrict__ B,
    float* __restrict__ C, int N)
{
    extern __shared__ char sm[];
    const uint32_t sb = smem_u32(sm);
    const int tid = threadIdx.x;
    const int lane = tid & 31, wid = tid >> 5;
    const int lg = lane >> 2, tq = lane & 3;
    const int mi = wid & 3, ni = wid >> 2;
    const size_t m0 = (size_t)blockIdx.y * 128, n0 = (size_t)blockIdx.x * 128;

    const uint32_t abase =
        (uint32_t)((mi * 32 + (lane & 15)) * 80 + (lane >> 4) * 16);
    const uint32_t bbase =
        (uint32_t)(10240 + (ni * 64 + (lane & 7) + ((lane >> 4) * 8)) * 80 +
                   ((lane >> 3) & 1) * 16);

    // loader: 128 rows x 64B per operand per stage; 2 x 16B chunks per thread
    const int lr = tid >> 1;            // row 0..127
    const int lh = tid & 1;             // which 32B half
    const f16* pA = A + (m0 + lr) * GK + lh * 16;
    const f16* pB = B + (n0 + lr) * GK + lh * 16;
    const uint32_t sdA = sb + lr * 80 + lh * 32;
    const uint32_t sdB = sb + 10240 + lr * 80 + lh * 32;

    float c[2][8][4];
#pragma unroll
    for (int a = 0; a < 2; a++)
#pragma unroll
        for (int b = 0; b < 8; b++)
#pragma unroll
            for (int d = 0; d < 4; d++) c[a][b][d] = 0.f;

    {
        CP16(sdA,      pA);
        CP16(sdA + 16, pA + 8);
        CP16(sdB,      pB);
        CP16(sdB + 16, pB + 8);
        CPCOMMIT();
    }

#pragma unroll 1
    for (int kt = 0; kt < GK / 32; kt++) {
        const int s = kt & 1;
        if (kt + 1 < GK / 32) {
            uint32_t dA = sdA + (s ^ 1) * GS_STAGE;
            uint32_t dB = sdB + (s ^ 1) * GS_STAGE;
            size_t off = (size_t)(kt + 1) * 32;
            CP16(dA,      pA + off);
            CP16(dA + 16, pA + off + 8);
            CP16(dB,      pB + off);
            CP16(dB + 16, pB + off + 8);
            CPCOMMIT();
            CPWAIT1();
        } else {
            CPWAIT0();
        }
        __syncthreads();

        const uint32_t stg = sb + s * GS_STAGE;
#pragma unroll
        for (int kk = 0; kk < 2; kk++) {
            uint32_t ah[2][4];
#pragma unroll
            for (int mt = 0; mt < 2; mt++)
                ldsm4(ah[mt], stg + abase + mt * (16 * 80) + kk * 32);
            uint32_t bb[8][2];
#pragma unroll
            for (int p = 0; p < 4; p++)
                ldsm4(&bb[2 * p][0], stg + bbase + p * (16 * 80) + kk * 32);
#pragma unroll
            for (int mt = 0; mt < 2; mt++)
#pragma unroll
                for (int nt = 0; nt < 8; nt++) mma_f32a(c[mt][nt], ah[mt], bb[nt]);
        }
        __syncthreads();
    }

#pragma unroll
    for (int mt = 0; mt < 2; mt++) {
        size_t r0 = m0 + mi * 32 + mt * 16 + lg;
#pragma unroll
        for (int nt = 0; nt < 8; nt++) {
            size_t col = n0 + ni * 64 + nt * 8 + tq * 2;
            *(float2*)(C + r0 * N + col) = make_float2(c[mt][nt][0], c[mt][nt][1]);
            *(float2*)(C + (r0 + 8) * N + col) = make_float2(c[mt][nt][2], c[mt][nt][3]);
        }
    }
}

// ---------------------------------------------------------------------------
// RoPE + fp16: q (slots 0-3, scaled) -> g_qh; k (slot 4) -> g_kh
// ---------------------------------------------------------------------------
__global__ __launch_bounds__(256) void rope_split_kernel(
    const float* __restrict__ cosb, const float* __restrict__ sinb)
{
    int idx = blockIdx.x * 256 + threadIdx.x;     // ROWS*4*5*64
    int d = idx & 63;
    int rg = idx >> 6;
    int slot = rg % 5;
    int q5 = rg / 5;
    int grp = q5 & 3;
    int row = q5 >> 2;
    int b = row >> 11, t = row & (Tn - 1);

    const float* p = g_qkv + (size_t)row * QKVW + grp * 768 + slot * 128 + d;
    float x1 = p[0], x2 = p[64];
    float cc = cosb[t * 64 + d], ss = sinb[t * 64 + d];
    float o1 = x1 * cc - x2 * ss;
    float o2 = x1 * ss + x2 * cc;

    if (slot < 4) {
        o1 *= QK_SCALE; o2 *= QK_SCALE;
        int head = grp * 4 + slot;
        size_t base = ((size_t)(b * 16 + head) * Tn + t) * 128 + d;
        g_qh[base]      = __float2half_rn(o1);
        g_qh[base + 64] = __float2half_rn(o2);
    } else {
        size_t base = ((size_t)(b * 4 + grp) * Tn + t) * 128 + d;
        g_kh[base]      = __float2half_rn(o1);
        g_kh[base + 64] = __float2half_rn(o2);
    }
}

// ---------------------------------------------------------------------------
// v: transpose -> g_vth [b][g][d][t]
// ---------------------------------------------------------------------------
__global__ __launch_bounds__(256) void vsplit_kernel() {
    __shared__ float tb[32][33];
    const int bg = blockIdx.z;
    const int t0 = blockIdx.x * 32, d0 = blockIdx.y * 32;
    const int tx = threadIdx.x, ty = threadIdx.y;
    const int b = bg >> 2, grp = bg & 3;
#pragma unroll
    for (int j = 0; j < 32; j += 8)
        tb[ty + j][tx] = g_qkv[((size_t)b * Tn + t0 + ty + j) * QKVW +
                               grp * 768 + 640 + d0 + tx];
    __syncthreads();
#pragma unroll
    for (int j = 0; j < 32; j += 8) {
        float v = tb[tx][ty + j];
        size_t o = ((size_t)bg * 128 + d0 + ty + j) * Tn + t0 + tx;
        g_vth[o] = __float2half_rn(v);
    }
}

// ---------------------------------------------------------------------------
// Flash attention, plain fp16 inputs, f32 accumulate.
// CTA = (qb, h, b): 128 q rows, 8 warps x m16. Key tiles of 64.
// smem: Qh [128 x 272B], Kh [64 x 272B], Vth [128 d x 144B] = 70656 B.
// ---------------------------------------------------------------------------
#define AQ_H 0
#define AK_H 34816
#define AV_H 52224
#define ATT_SMEM 70656

__global__ __launch_bounds__(256, 1) void attn_kernel() {
    extern __shared__ char sm[];
    const uint32_t sb = smem_u32(sm);
    const int tid = threadIdx.x;
    const int lane = tid & 31, wid = tid >> 5;
    const int lg = lane >> 2, tq = lane & 3;
    const int qb = blockIdx.x, h = blockIdx.y, b = blockIdx.z;
    const int grp = h >> 2;

    const uint32_t qbase = sb + AQ_H + (wid * 16 + (lane & 15)) * 272 +
                           (lane >> 4) * 16;
    const uint32_t kbase = sb + AK_H + ((lane & 7) + ((lane >> 4) * 8)) * 272 +
                           ((lane >> 3) & 1) * 16;
    const uint32_t vbase = sb + AV_H + ((lane & 7) + ((lane >> 4) * 8)) * 144 +
                           ((lane >> 3) & 1) * 16;

    // load Q, 128 x 128 f16
    {
        const f16* qhp = g_qh + ((size_t)(b * 16 + h) * Tn + qb * 128) * 128;
#pragma unroll
        for (int it = 0; it < 8; it++) {
            int idx = it * 256 + tid;
            int r = idx >> 4, hx = idx & 15;
            *(uint4*)(sm + AQ_H + r * 272 + hx * 16) =
                *(const uint4*)(qhp + (size_t)r * 128 + hx * 8);
        }
    }

    float o[16][4];
#pragma unroll
    for (int i = 0; i < 16; i++)
#pragma unroll
        for (int j = 0; j < 4; j++) o[i][j] = 0.f;
    float m0 = __int_as_float(0xff800000), m1 = m0;
    float l0 = 0.f, l1 = 0.f;

    const f16* khp = g_kh + (size_t)(b * 4 + grp) * Tn * 128;
    const f16* vhp = g_vth + (size_t)(b * 4 + grp) * 128 * Tn;

#pragma unroll 1
    for (int kt = 0; kt < Tn / 64; kt++) {
        __syncthreads();
#pragma unroll
        for (int it = 0; it < 4; it++) {
            int idx = it * 256 + tid;
            int r = idx >> 4, hx = idx & 15;
            size_t go = ((size_t)kt * 64 + r) * 128 + hx * 8;
            *(uint4*)(sm + AK_H + r * 272 + hx * 16) = *(const uint4*)(khp + go);
        }
#pragma unroll
        for (int it = 0; it < 4; it++) {
            int idx = it * 256 + tid;
            int r = idx >> 3, hx = idx & 7;
            size_t go = (size_t)r * Tn + kt * 64 + hx * 8;
            *(uint4*)(sm + AV_H + r * 144 + hx * 16) = *(const uint4*)(vhp + go);
        }
        __syncthreads();

        // ---- S = Q Kh^T, f32 acc ----
        float s[8][4];
#pragma unroll
        for (int i = 0; i < 8; i++)
#pragma unroll
            for (int j = 0; j < 4; j++) s[i][j] = 0.f;

#pragma unroll
        for (int kk = 0; kk < 8; kk++) {
            uint32_t qah[4];
            ldsm4(qah, qbase + kk * 32);
            uint32_t kb[8][2];
#pragma unroll
            for (int p = 0; p < 4; p++)
                ldsm4(&kb[2 * p][0], kbase + p * (16 * 272) + kk * 32);
#pragma unroll
            for (int nt = 0; nt < 8; nt++) mma_f32a(s[nt], qah, kb[nt]);
        }

        // ---- online softmax (2 rows per lane: lg, lg+8) ----
        float mx0 = s[0][0], mx1 = s[0][2];
#pragma unroll
        for (int nt = 0; nt < 8; nt++) {
            mx0 = fmaxf(mx0, fmaxf(s[nt][0], s[nt][1]));
            mx1 = fmaxf(mx1, fmaxf(s[nt][2], s[nt][3]));
        }
        mx0 = fmaxf(mx0, __shfl_xor_sync(0xffffffffu, mx0, 1));
        mx0 = fmaxf(mx0, __shfl_xor_sync(0xffffffffu, mx0, 2));
        mx1 = fmaxf(mx1, __shfl_xor_sync(0xffffffffu, mx1, 1));
        mx1 = fmaxf(mx1, __shfl_xor_sync(0xffffffffu, mx1, 2));
        float mn0 = fmaxf(m0, mx0), mn1 = fmaxf(m1, mx1);
        float cr0 = ex2f(m0 - mn0), cr1 = ex2f(m1 - mn1);
        m0 = mn0; m1 = mn1;
        float sum0 = 0.f, sum1 = 0.f;
#pragma unroll
        for (int nt = 0; nt < 8; nt++) {
            s[nt][0] = ex2f(s[nt][0] - mn0);
            s[nt][1] = ex2f(s[nt][1] - mn0);
            s[nt][2] = ex2f(s[nt][2] - mn1);
            s[nt][3] = ex2f(s[nt][3] - mn1);
            sum0 += s[nt][0] + s[nt][1];
            sum1 += s[nt][2] + s[nt][3];
        }
        sum0 += __shfl_xor_sync(0xffffffffu, sum0, 1);
        sum0 += __shfl_xor_sync(0xffffffffu, sum0, 2);
        sum1 += __shfl_xor_sync(0xffffffffu, sum1, 1);
        sum1 += __shfl_xor_sync(0xffffffffu, sum1, 2);
        l0 = l0 * cr0 + sum0;
        l1 = l1 * cr1 + sum1;
#pragma unroll
        for (int nt = 0; nt < 16; nt++) {
            o[nt][0] *= cr0; o[nt][1] *= cr0;
            o[nt][2] *= cr1; o[nt][3] *= cr1;
        }

        // ---- O += Ph Vh, f32 acc ----
#pragma unroll
        for (int kk = 0; kk < 4; kk++) {
            uint32_t ph[4];
#pragma unroll
            for (int q2 = 0; q2 < 2; q2++) {
                ph[2 * q2]     = pkh2(s[2 * kk + q2][0], s[2 * kk + q2][1]);
                ph[2 * q2 + 1] = pkh2(s[2 * kk + q2][2], s[2 * kk + q2][3]);
            }
#pragma unroll
            for (int blk = 0; blk < 2; blk++) {
                uint32_t vb[8][2];
#pragma unroll
                for (int p = 0; p < 4; p++)
                    ldsm4(&vb[2 * p][0], vbase + (blk * 64 + p * 16) * 144 + kk * 32);
#pragma unroll
                for (int j = 0; j < 8; j++) mma_f32a(o[blk * 8 + j], ph, vb[j]);
            }
        }
    }

    // ---- epilogue: y = O / l -> fp16 ----
    float i0 = 1.f / l0, i1 = 1.f / l1;
    size_t row0 = (size_t)b * Tn + qb * 128 + wid * 16 + lg;
#pragma unroll
    for (int nt = 0; nt < 16; nt++) {
        int col = h * 128 + nt * 8 + tq * 2;
        *(uint32_t*)(g_yh + row0 * Cn + col) =
            pkh2(o[nt][0] * i0, o[nt][1] * i0);
        *(uint32_t*)(g_yh + (row0 + 8) * Cn + col) =
            pkh2(o[nt][2] * i1, o[nt][3] * i1);
    }
}

// ---------------------------------------------------------------------------
extern "C" void kernel_launch(void* const* d_in, const int* in_sizes, int n_in,
                              void* d_out, int out_size) {
    const float* x      = (const float*)d_in[0];
    const float* cosb   = (const float*)d_in[1];
    const float* sinb   = (const float*)d_in[2];
    const float* w_attn = (const float*)d_in[3];
    const float* w_proj = (const float*)d_in[4];
    float* out = (float*)d_out;
    (void)in_sizes; (void)n_in; (void)out_size;

    (void)cudaFuncSetAttribute(hgemm1_kernel,
                               cudaFuncAttributeMaxDynamicSharedMemorySize, GSM);
    (void)cudaFuncSetAttribute(attn_kernel,
                               cudaFuncAttributeMaxDynamicSharedMemorySize, ATT_SMEM);

    float* qkvp = nullptr;
    f16 *xh, *wah, *wph, *yh;
    (void)cudaGetSymbolAddress((void**)&qkvp, g_qkv);
    (void)cudaGetSymbolAddress((void**)&xh, g_xh);
    (void)cudaGetSymbolAddress((void**)&wah, g_wah);
    (void)cudaGetSymbolAddress((void**)&wph, g_wph);
    (void)cudaGetSymbolAddress((void**)&yh, g_yh);

    // 0. fp16 conversions
    splitx_kernel<<<(ROWS * GK / 4) / 256, 256>>>(x);
    wsplit_kernel<<<dim3(QKVW / 32, GK / 32), dim3(32, 8)>>>(w_attn, wah, QKVW);
    wsplit_kernel<<<dim3(Cn / 32, GK / 32), dim3(32, 8)>>>(w_proj, wph, Cn);
    // 1. qkv = x @ w_attn (fp16, 128x128 tiles)
    hgemm1_kernel<<<dim3(QKVW / 128, ROWS / 128), 256, GSM>>>(xh, wah, qkvp, QKVW);
    // 2. RoPE -> q, k (fp16)
    rope_split_kernel<<<(ROWS * 4 * 5 * 64) / 256, 256>>>(cosb, sinb);
    // 3. v transpose (fp16)
    vsplit_kernel<<<dim3(Tn / 32, 4, 8), dim3(32, 8)>>>();
    // 4. attention -> yh
    attn_kernel<<<dim3(Tn / 128, 16, 2), 256, ATT_SMEM>>>();
    // 5. out = y @ w_proj (fp16, 128x128 tiles)
    hgemm1_kernel<<<dim3(Cn / 128, ROWS / 128), 256, GSM>>>(yh, wph, out, Cn);
}